// round 15
// baseline (speedup 1.0000x reference)
#include <cuda_runtime.h>
#include <cuda_fp16.h>
#include <math.h>

#define IMG     512
#define NVIEW   360
#define NPAIR   180          // view pairs (v, v+180): angles differ by exactly pi/2
#define NQ      16           // row-slices per view-pair
#define RQ      (IMG / NQ)   // 32 rows per CTA
#define PW      516          // gmem line stride (entries 0..513 valid)
#define N1      (514 * PW)
#define OUTN    (2 * IMG * NVIEW)

// Interleaved fp16 dup-pair images, batch-interleaved, zeros baked into borders.
// Entry i of padded line p = ( I_lo, I_hi, J_lo, J_hi ) where each is half2(b0,b1),
// lo = pixel i-1, hi = pixel i, and J[r][c] = I[511-c][r] (90-deg rotation pairs
// view v with view v+180 whose angle differs by exactly pi/2).
__device__ uint4 g_ir[N1];   // row orientation
__device__ uint4 g_ic[N1];   // col orientation
__device__ float4 g_vp[NVIEW];
__device__ int    g_vmode[NVIEW];

__device__ __forceinline__ unsigned h2pix(const float* __restrict__ x, int y, int xx) {
    float2 f = make_float2(0.f, 0.f);
    if ((unsigned)y < 512u && (unsigned)xx < 512u) {
        f.x = x[y * IMG + xx];
        f.y = x[IMG * IMG + y * IMG + xx];
    }
    __half2 h = __float22half2_rn(f);
    return *reinterpret_cast<unsigned*>(&h);
}

__global__ void prep_kernel(const float* __restrict__ x, float* __restrict__ out) {
    int idx = blockIdx.x * blockDim.x + threadIdx.x;

    if (idx < NVIEW) {
        double ang = -M_PI * (double)(idx + 1) / (double)NVIEW - M_PI;
        float c = (float)cos(ang);
        float s = (float)sin(ang);
        if (fabsf(c) >= fabsf(s)) g_vp[idx] = make_float4(c, -s, s, c),  g_vmode[idx] = 0;
        else                      g_vp[idx] = make_float4(-s, c, c, s),  g_vmode[idx] = 1;
    }

    if (idx < OUTN) out[idx] = 0.0f;   // fp_kernel accumulates atomically

    if (idx < N1) {
        int p = idx / PW;
        int i = idx - p * PW;
        // row orientation: I part = image row p-1; J part = J row p-1 = I[512-i..][p-1]
        g_ir[idx] = make_uint4(h2pix(x, p - 1,   i - 1), h2pix(x, p - 1,   i),
                               h2pix(x, 512 - i, p - 1), h2pix(x, 511 - i, p - 1));
        // col orientation: I part = image col p-1; J part = J col p-1 = I[512-p][i-1..i]
        g_ic[idx] = make_uint4(h2pix(x, i - 1,   p - 1), h2pix(x, i,       p - 1),
                               h2pix(x, 512 - p, i - 1), h2pix(x, 512 - p, i));
    }
}

__device__ __forceinline__ void lerpacc(uint4 e, float wq, float wp,
                                        float& a0, float& a1, float& a2, float& a3) {
    __half2 wqh = __float2half2_rn(wq);
    __half2 mI = __hfma2(wqh, __hsub2(*(const __half2*)&e.y, *(const __half2*)&e.x),
                         *(const __half2*)&e.x);
    __half2 mJ = __hfma2(wqh, __hsub2(*(const __half2*)&e.w, *(const __half2*)&e.z),
                         *(const __half2*)&e.z);
    float2 fI = __half22float2(mI);
    float2 fJ = __half22float2(mJ);
    a0 = fmaf(wp, fI.x, a0);
    a1 = fmaf(wp, fI.y, a1);
    a2 = fmaf(wp, fJ.x, a2);
    a3 = fmaf(wp, fJ.y, a3);
}

__global__ __launch_bounds__(512, 4) void fp_kernel(float* __restrict__ out) {
    int v = blockIdx.x;               // primary view; pair view = v + 180
    int q = blockIdx.y;
    int w = threadIdx.x;
    int r0 = q * RQ;

    float4 vp = g_vp[v];
    const uint4* __restrict__ G = g_vmode[v] ? g_ic : g_ir;

    float a    = vp.x;
    float bc   = vp.y;
    float absa = fabsf(a);
    float c2   = 1.0f - 2.0f * absa;            // for wp2
    float wr   = (float)w - 255.5f;
    float A    = fmaf(vp.z, wr, 255.5f);
    float B    = fmaf(vp.w, wr, 255.5f);
    float Bp   = fmaf(-255.5f, bc, B);          // Q = bc*hb + Bp
    float inv_a = 1.0f / a;

    float a0 = 0.f, a1 = 0.f, a2 = 0.f, a3 = 0.f;

    // hc at r = r0, advanced incrementally (drift << window margin)
    float hcv = fmaf((float)r0 - A, inv_a, 255.5f);

    // padded line for image row r0, pre-offset by +1 so px in [-1,512] indexes directly
    const uint4* linep = G + (size_t)(r0 + 1) * PW + 1;

    #pragma unroll 4
    for (int st = 0; st < RQ; st++) {
        // hc solves P(h)=r; open support spans < 2*sqrt(2); 3 candidates
        // from hb = ceil(hc - 1.4146) provably cover it.
        float hb = ceilf(hcv - 1.4146f);
        float d  = hb - hcv;                  // in (-1.4146, -0.4146]

        // ---- phase A: addresses + all three loads in flight ----
        float Qc0 = fminf(fmaxf(fmaf(bc, hb, Bp),        -1.0f), 512.0f);  // clamps land on zero pads
        float Qc1 = fminf(fmaxf(fmaf(bc, hb + 1.0f, Bp), -1.0f), 512.0f);
        float Qc2 = fminf(fmaxf(fmaf(bc, hb + 2.0f, Bp), -1.0f), 512.0f);
        float f0 = floorf(Qc0);
        float f1 = floorf(Qc1);
        float f2 = floorf(Qc2);
        uint4 e0 = __ldg(&linep[(int)f0]);
        uint4 e1 = __ldg(&linep[(int)f1]);
        uint4 e2 = __ldg(&linep[(int)f2]);

        // ---- phase B: weights + math ----
        float wp0 = fmaxf(fmaf( absa, d,               1.0f), 0.0f);  // d < 0
        float wp1 = fmaxf(fmaf(-absa, fabsf(d + 1.0f), 1.0f), 0.0f);
        float wp2 = fmaxf(fmaf(-absa, d,               c2),   0.0f);  // = 1-|a|(d+2)

        if (hb < 0.0f || hb > 509.0f) {       // rare edge rows (float test: no int h0 needed)
            if (hb < 0.0f   || hb > 511.0f) wp0 = 0.0f;
            if (hb < -1.0f  || hb > 510.0f) wp1 = 0.0f;
            if (hb < -2.0f  || hb > 509.0f) wp2 = 0.0f;
        }

        lerpacc(e0, Qc0 - f0, wp0, a0, a1, a2, a3);
        lerpacc(e1, Qc1 - f1, wp1, a0, a1, a2, a3);
        lerpacc(e2, Qc2 - f2, wp2, a0, a1, a2, a3);

        hcv += inv_a;
        linep += PW;
    }

    int v2 = v + NPAIR;
    atomicAdd(&out[w * NVIEW + v],                a0 * 0.5f);
    atomicAdd(&out[IMG * NVIEW + w * NVIEW + v],  a1 * 0.5f);
    atomicAdd(&out[w * NVIEW + v2],               a2 * 0.5f);
    atomicAdd(&out[IMG * NVIEW + w * NVIEW + v2], a3 * 0.5f);
}

extern "C" void kernel_launch(void* const* d_in, const int* in_sizes, int n_in,
                              void* d_out, int out_size) {
    const float* x = (const float*)d_in[0];
    float* out = (float*)d_out;

    int nprep = OUTN;   // >= N1 and >= NVIEW
    prep_kernel<<<(nprep + 255) / 256, 256>>>(x, out);

    dim3 grid(NPAIR, NQ);
    fp_kernel<<<grid, 512>>>(out);
}

// round 16
// speedup vs baseline: 1.0600x; 1.0600x over previous
#include <cuda_runtime.h>
#include <cuda_fp16.h>
#include <math.h>

#define IMG     512
#define NVIEW   360
#define NPAIR   180          // view pairs (v, v+180): angles differ by exactly pi/2
#define NQ      16           // row-slices per view-pair
#define RQ      (IMG / NQ)   // 32 rows per CTA
#define PADL    184          // entries left of pixel 0 (covers px >= -183)
#define WB      880          // entry line width (covers px <= 693)
#define NLINE   514
#define N1      (NLINE * WB)
#define OUTN    (2 * IMG * NVIEW)
#define MAGICF  12582912.0f  // 2^23 + 2^22
#define MAGICI  0x4B400000

// fp16 avg/diff pair images, batch-interleaved half2(b0,b1), zeros baked into the
// (wide) borders. Entry with pixel-index px on line p describes pixels (px, px+1):
//   e = ( avgI, diffI, avgJ, diffJ ),  avg = (lo+hi)/2, diff = hi-lo
// J[r][c] = I[511-c][r]: 90-deg rotation pairs view v with v+180 (angles differ
// by exactly pi/2). Bilinear sample = avg + u*diff with u = (Q-0.5) - round(Q-0.5).
__device__ uint4 g_ir[N1];   // row orientation
__device__ uint4 g_ic[N1];   // col orientation
__device__ float4 g_vp[NVIEW];
__device__ int    g_vmode[NVIEW];

__device__ __forceinline__ float2 pixf(const float* __restrict__ x, int y, int xx) {
    float2 f = make_float2(0.f, 0.f);
    if ((unsigned)y < 512u && (unsigned)xx < 512u) {
        f.x = x[y * IMG + xx];
        f.y = x[IMG * IMG + y * IMG + xx];
    }
    return f;
}

__device__ __forceinline__ unsigned packh2(float a, float b) {
    __half2 h = __float22half2_rn(make_float2(a, b));
    return *reinterpret_cast<unsigned*>(&h);
}

__global__ void prep_kernel(const float* __restrict__ x, float* __restrict__ out) {
    int idx = blockIdx.x * blockDim.x + threadIdx.x;

    if (idx < NVIEW) {
        double ang = -M_PI * (double)(idx + 1) / (double)NVIEW - M_PI;
        float c = (float)cos(ang);
        float s = (float)sin(ang);
        if (fabsf(c) >= fabsf(s)) g_vp[idx] = make_float4(c, -s, s, c),  g_vmode[idx] = 0;
        else                      g_vp[idx] = make_float4(-s, c, c, s),  g_vmode[idx] = 1;
    }

    if (idx < OUTN) out[idx] = 0.0f;   // fp_kernel accumulates atomically

    if (idx < 2 * N1) {
        int o   = (idx >= N1);
        int rem = idx - o * N1;
        int p   = rem / WB;
        int i   = rem - p * WB;
        int px  = i - PADL;            // entry covers pixels (px, px+1)
        float2 loI, hiI, loJ, hiJ;
        if (o == 0) {   // row orientation: line p = image row p-1, px over x
            loI = pixf(x, p - 1, px);        hiI = pixf(x, p - 1, px + 1);
            loJ = pixf(x, 511 - px, p - 1);  hiJ = pixf(x, 510 - px, p - 1);
        } else {        // col orientation: line p = image col p-1, px over y
            loI = pixf(x, px, p - 1);        hiI = pixf(x, px + 1, p - 1);
            loJ = pixf(x, 512 - p, px);      hiJ = pixf(x, 512 - p, px + 1);
        }
        uint4 e;
        e.x = packh2(0.5f * (loI.x + hiI.x), 0.5f * (loI.y + hiI.y));
        e.y = packh2(hiI.x - loI.x,          hiI.y - loI.y);
        e.z = packh2(0.5f * (loJ.x + hiJ.x), 0.5f * (loJ.y + hiJ.y));
        e.w = packh2(hiJ.x - loJ.x,          hiJ.y - loJ.y);
        if (o == 0) g_ir[rem] = e;
        else        g_ic[rem] = e;
    }
}

__device__ __forceinline__ void lerpacc(uint4 e, float u, float wp,
                                        unsigned long long& accI,
                                        unsigned long long& accJ) {
    __half2 uh = __float2half2_rn(u);
    __half2 mI = __hfma2(uh, *(const __half2*)&e.y, *(const __half2*)&e.x);
    __half2 mJ = __hfma2(uh, *(const __half2*)&e.w, *(const __half2*)&e.z);
    float2 fI = __half22float2(mI);
    float2 fJ = __half22float2(mJ);
    unsigned long long wpp, mIp, mJp;
    asm("mov.b64 %0, {%1, %2};" : "=l"(wpp) : "f"(wp),   "f"(wp));
    asm("mov.b64 %0, {%1, %2};" : "=l"(mIp) : "f"(fI.x), "f"(fI.y));
    asm("mov.b64 %0, {%1, %2};" : "=l"(mJp) : "f"(fJ.x), "f"(fJ.y));
    asm("fma.rn.f32x2 %0, %1, %2, %0;" : "+l"(accI) : "l"(wpp), "l"(mIp));
    asm("fma.rn.f32x2 %0, %1, %2, %0;" : "+l"(accJ) : "l"(wpp), "l"(mJp));
}

__global__ __launch_bounds__(512) void fp_kernel(float* __restrict__ out) {
    int v = blockIdx.x;               // primary view; pair view = v + 180
    int q = blockIdx.y;
    int w = threadIdx.x;
    int r0 = q * RQ;

    float4 vp = g_vp[v];
    const uint4* __restrict__ G = g_vmode[v] ? g_ic : g_ir;

    float a    = vp.x;
    float bc   = vp.y;
    float absa = fabsf(a);
    float c2   = 1.0f - 2.0f * absa;            // for wp2
    float wr   = (float)w - 255.5f;
    float A    = fmaf(vp.z, wr, 255.5f);
    float B    = fmaf(vp.w, wr, 255.5f);
    // Q(h) = bc*(h - 255.5) + B; shifted Qs = Q - 0.5 = bc*h + Bp5
    float Bp5  = fmaf(-255.5f, bc, B) - 0.5f;
    float inv_a = 1.0f / a;

    unsigned long long accI = 0ULL, accJ = 0ULL;

    // hc at r = r0, advanced incrementally (drift << window margin)
    float hcv = fmaf((float)r0 - A, inv_a, 255.5f);

    // entry line for image row r0, pointing at pixel-index 0
    const uint4* linep = G + (size_t)(r0 + 1) * WB + PADL;

    #pragma unroll 4
    for (int st = 0; st < RQ; st++) {
        // hc solves P(h)=r; open support spans < 2*sqrt(2); 3 candidates
        // from hb = ceil(hc - 1.4146) provably cover it.
        float hb  = ceilf(hcv - 1.4146f);
        float d   = hb - hcv;                 // in (-1.4146, -0.4146]
        float hbc = fminf(fmaxf(hb, -2.0f), 512.0f);   // address-only clamp

        // ---- phase A: shifted coords, magic round, all three loads in flight ----
        float Qs0 = fmaf(bc, hbc, Bp5);
        float Qs1 = Qs0 + bc;
        float Qs2 = Qs1 + bc;
        float t0 = __fadd_rn(Qs0, MAGICF);
        float t1 = __fadd_rn(Qs1, MAGICF);
        float t2 = __fadd_rn(Qs2, MAGICF);
        int px0 = __float_as_int(t0) - MAGICI;         // = round(Qs) in [-183, 693]
        int px1 = __float_as_int(t1) - MAGICI;
        int px2 = __float_as_int(t2) - MAGICI;
        uint4 e0 = __ldg(&linep[px0]);
        uint4 e1 = __ldg(&linep[px1]);
        uint4 e2 = __ldg(&linep[px2]);

        // ---- phase B: weights + math ----
        float u0 = Qs0 - __fadd_rn(t0, -MAGICF);       // in [-0.5, 0.5]
        float u1 = Qs1 - __fadd_rn(t1, -MAGICF);
        float u2 = Qs2 - __fadd_rn(t2, -MAGICF);

        float wp0 = fmaxf(fmaf( absa, d,               1.0f), 0.0f);  // d < 0
        float wp1 = fmaxf(fmaf(-absa, fabsf(d + 1.0f), 1.0f), 0.0f);
        float wp2 = fmaxf(fmaf(-absa, d,               c2),   0.0f);  // = 1-|a|(d+2)

        if (hb < 0.0f || hb > 509.0f) {       // rare edge rows
            if (hb < 0.0f  || hb > 511.0f) wp0 = 0.0f;
            if (hb < -1.0f || hb > 510.0f) wp1 = 0.0f;
            if (hb < -2.0f || hb > 509.0f) wp2 = 0.0f;
        }

        lerpacc(e0, u0, wp0, accI, accJ);
        lerpacc(e1, u1, wp1, accI, accJ);
        lerpacc(e2, u2, wp2, accI, accJ);

        hcv += inv_a;
        linep += WB;
    }

    float aI0, aI1, aJ0, aJ1;
    asm("mov.b64 {%0, %1}, %2;" : "=f"(aI0), "=f"(aI1) : "l"(accI));
    asm("mov.b64 {%0, %1}, %2;" : "=f"(aJ0), "=f"(aJ1) : "l"(accJ));

    int v2 = v + NPAIR;
    atomicAdd(&out[w * NVIEW + v],                aI0 * 0.5f);
    atomicAdd(&out[IMG * NVIEW + w * NVIEW + v],  aI1 * 0.5f);
    atomicAdd(&out[w * NVIEW + v2],               aJ0 * 0.5f);
    atomicAdd(&out[IMG * NVIEW + w * NVIEW + v2], aJ1 * 0.5f);
}

extern "C" void kernel_launch(void* const* d_in, const int* in_sizes, int n_in,
                              void* d_out, int out_size) {
    const float* x = (const float*)d_in[0];
    float* out = (float*)d_out;

    int nprep = 2 * N1;   // > OUTN and > NVIEW
    prep_kernel<<<(nprep + 255) / 256, 256>>>(x, out);

    dim3 grid(NPAIR, NQ);
    fp_kernel<<<grid, 512>>>(out);
}

// round 17
// speedup vs baseline: 1.0905x; 1.0287x over previous
#include <cuda_runtime.h>
#include <cuda_fp16.h>
#include <math.h>

#define IMG     512
#define NVIEW   360
#define NPAIR   180          // view pairs (v, v+180): angles differ by exactly pi/2
#define NQ      16           // row-slices per view-pair
#define RQ      (IMG / NQ)   // 32 rows per CTA
#define PADL    184          // entries left of pixel 0 (covers px >= -183)
#define WB      880          // entry line width (covers px <= 693)
#define NLINE   514
#define N1      (NLINE * WB)
#define OUTN    (2 * IMG * NVIEW)
#define MAGICF  12582912.0f  // 2^23 + 2^22
#define MAGICI  0x4B400000

// fp16 avg/diff pair images, batch-interleaved half2(b0,b1), zeros baked into the
// (wide) borders. Entry with pixel-index px on line p describes pixels (px, px+1):
//   e = ( avgI, diffI, avgJ, diffJ ),  avg = (lo+hi)/2, diff = hi-lo
// J[r][c] = I[511-c][r]: 90-deg rotation pairs view v with v+180 (angles differ
// by exactly pi/2). Bilinear sample = avg + u*diff with u = (Q-0.5) - round(Q-0.5).
__device__ uint4 g_ir[N1];   // row orientation
__device__ uint4 g_ic[N1];   // col orientation
__device__ float4 g_vp[NVIEW];
__device__ int    g_vmode[NVIEW];

__device__ __forceinline__ float2 pixf(const float* __restrict__ x, int y, int xx) {
    float2 f = make_float2(0.f, 0.f);
    if ((unsigned)y < 512u && (unsigned)xx < 512u) {
        f.x = x[y * IMG + xx];
        f.y = x[IMG * IMG + y * IMG + xx];
    }
    return f;
}

__device__ __forceinline__ unsigned packh2(float a, float b) {
    __half2 h = __float22half2_rn(make_float2(a, b));
    return *reinterpret_cast<unsigned*>(&h);
}

__global__ void prep_kernel(const float* __restrict__ x, float* __restrict__ out) {
    int idx = blockIdx.x * blockDim.x + threadIdx.x;

    if (idx < NVIEW) {
        double ang = -M_PI * (double)(idx + 1) / (double)NVIEW - M_PI;
        float c = (float)cos(ang);
        float s = (float)sin(ang);
        if (fabsf(c) >= fabsf(s)) g_vp[idx] = make_float4(c, -s, s, c),  g_vmode[idx] = 0;
        else                      g_vp[idx] = make_float4(-s, c, c, s),  g_vmode[idx] = 1;
    }

    if (idx < OUTN) out[idx] = 0.0f;   // fp_kernel accumulates atomically

    if (idx < 2 * N1) {
        int o   = (idx >= N1);
        int rem = idx - o * N1;
        int p   = rem / WB;
        int i   = rem - p * WB;
        int px  = i - PADL;            // entry covers pixels (px, px+1)
        float2 loI, hiI, loJ, hiJ;
        if (o == 0) {   // row orientation: line p = image row p-1, px over x
            loI = pixf(x, p - 1, px);        hiI = pixf(x, p - 1, px + 1);
            loJ = pixf(x, 511 - px, p - 1);  hiJ = pixf(x, 510 - px, p - 1);
        } else {        // col orientation: line p = image col p-1, px over y
            loI = pixf(x, px, p - 1);        hiI = pixf(x, px + 1, p - 1);
            loJ = pixf(x, 512 - p, px);      hiJ = pixf(x, 512 - p, px + 1);
        }
        uint4 e;
        e.x = packh2(0.5f * (loI.x + hiI.x), 0.5f * (loI.y + hiI.y));
        e.y = packh2(hiI.x - loI.x,          hiI.y - loI.y);
        e.z = packh2(0.5f * (loJ.x + hiJ.x), 0.5f * (loJ.y + hiJ.y));
        e.w = packh2(hiJ.x - loJ.x,          hiJ.y - loJ.y);
        if (o == 0) g_ir[rem] = e;
        else        g_ic[rem] = e;
    }
}

__device__ __forceinline__ void lerpacc(uint4 e, float u, float wp,
                                        unsigned long long& accI,
                                        unsigned long long& accJ) {
    __half2 uh = __float2half2_rn(u);
    __half2 mI = __hfma2(uh, *(const __half2*)&e.y, *(const __half2*)&e.x);
    __half2 mJ = __hfma2(uh, *(const __half2*)&e.w, *(const __half2*)&e.z);
    float2 fI = __half22float2(mI);
    float2 fJ = __half22float2(mJ);
    unsigned long long wpp, mIp, mJp;
    asm("mov.b64 %0, {%1, %2};" : "=l"(wpp) : "f"(wp),   "f"(wp));
    asm("mov.b64 %0, {%1, %2};" : "=l"(mIp) : "f"(fI.x), "f"(fI.y));
    asm("mov.b64 %0, {%1, %2};" : "=l"(mJp) : "f"(fJ.x), "f"(fJ.y));
    asm("fma.rn.f32x2 %0, %1, %2, %0;" : "+l"(accI) : "l"(wpp), "l"(mIp));
    asm("fma.rn.f32x2 %0, %1, %2, %0;" : "+l"(accJ) : "l"(wpp), "l"(mJp));
}

__global__ __launch_bounds__(256) void fp_kernel(float* __restrict__ out) {
    int v = blockIdx.x;               // primary view; pair view = v + 180
    int q = blockIdx.y;
    int w = threadIdx.x + (blockIdx.z << 8);   // detector bin 0..511
    int r0 = q * RQ;

    float4 vp = g_vp[v];
    const uint4* __restrict__ G = g_vmode[v] ? g_ic : g_ir;

    float a    = vp.x;
    float bc   = vp.y;
    float absa = fabsf(a);
    float c2   = 1.0f - 2.0f * absa;            // for wp2
    float wr   = (float)w - 255.5f;
    float A    = fmaf(vp.z, wr, 255.5f);
    float B    = fmaf(vp.w, wr, 255.5f);
    // Q(h) = bc*(h - 255.5) + B; shifted Qs = Q - 0.5 = bc*h + Bp5
    float Bp5  = fmaf(-255.5f, bc, B) - 0.5f;
    float inv_a = 1.0f / a;

    unsigned long long accI = 0ULL, accJ = 0ULL;

    // hc at r = r0, advanced incrementally (drift << window margin)
    float hcv = fmaf((float)r0 - A, inv_a, 255.5f);

    // entry line for image row r0, pointing at pixel-index 0
    const uint4* linep = G + (size_t)(r0 + 1) * WB + PADL;

    #pragma unroll 4
    for (int st = 0; st < RQ; st++) {
        // hc solves P(h)=r; open support spans < 2*sqrt(2); 3 candidates
        // from hb = ceil(hc - 1.4146) provably cover it.
        float hb  = ceilf(hcv - 1.4146f);
        float d   = hb - hcv;                 // in (-1.4146, -0.4146]
        float hbc = fminf(fmaxf(hb, -2.0f), 512.0f);   // address-only clamp

        // ---- phase A: shifted coords, magic round, all three loads in flight ----
        float Qs0 = fmaf(bc, hbc, Bp5);
        float Qs1 = Qs0 + bc;
        float Qs2 = Qs1 + bc;
        float t0 = __fadd_rn(Qs0, MAGICF);
        float t1 = __fadd_rn(Qs1, MAGICF);
        float t2 = __fadd_rn(Qs2, MAGICF);
        int px0 = __float_as_int(t0) - MAGICI;         // = round(Qs) in [-183, 693]
        int px1 = __float_as_int(t1) - MAGICI;
        int px2 = __float_as_int(t2) - MAGICI;
        uint4 e0 = __ldg(&linep[px0]);
        uint4 e1 = __ldg(&linep[px1]);
        uint4 e2 = __ldg(&linep[px2]);

        // ---- phase B: weights + math ----
        float u0 = Qs0 - __fadd_rn(t0, -MAGICF);       // in [-0.5, 0.5]
        float u1 = Qs1 - __fadd_rn(t1, -MAGICF);
        float u2 = Qs2 - __fadd_rn(t2, -MAGICF);

        float wp0 = fmaxf(fmaf( absa, d,               1.0f), 0.0f);  // d < 0
        float wp1 = fmaxf(fmaf(-absa, fabsf(d + 1.0f), 1.0f), 0.0f);
        float wp2 = fmaxf(fmaf(-absa, d,               c2),   0.0f);  // = 1-|a|(d+2)

        if (hb < 0.0f || hb > 509.0f) {       // rare edge rows
            if (hb < 0.0f  || hb > 511.0f) wp0 = 0.0f;
            if (hb < -1.0f || hb > 510.0f) wp1 = 0.0f;
            if (hb < -2.0f || hb > 509.0f) wp2 = 0.0f;
        }

        lerpacc(e0, u0, wp0, accI, accJ);
        lerpacc(e1, u1, wp1, accI, accJ);
        lerpacc(e2, u2, wp2, accI, accJ);

        hcv += inv_a;
        linep += WB;
    }

    float aI0, aI1, aJ0, aJ1;
    asm("mov.b64 {%0, %1}, %2;" : "=f"(aI0), "=f"(aI1) : "l"(accI));
    asm("mov.b64 {%0, %1}, %2;" : "=f"(aJ0), "=f"(aJ1) : "l"(accJ));

    int v2 = v + NPAIR;
    atomicAdd(&out[w * NVIEW + v],                aI0 * 0.5f);
    atomicAdd(&out[IMG * NVIEW + w * NVIEW + v],  aI1 * 0.5f);
    atomicAdd(&out[w * NVIEW + v2],               aJ0 * 0.5f);
    atomicAdd(&out[IMG * NVIEW + w * NVIEW + v2], aJ1 * 0.5f);
}

extern "C" void kernel_launch(void* const* d_in, const int* in_sizes, int n_in,
                              void* d_out, int out_size) {
    const float* x = (const float*)d_in[0];
    float* out = (float*)d_out;

    int nprep = 2 * N1;   // > OUTN and > NVIEW
    prep_kernel<<<(nprep + 255) / 256, 256>>>(x, out);

    dim3 grid(NPAIR, NQ, 2);
    fp_kernel<<<grid, 256>>>(out);
}